// round 9
// baseline (speedup 1.0000x reference)
#include <cuda_runtime.h>

#define NN 512
#define DD 32
#define HD 16              // d's per thread (2 threads per neuron)
#define TT 8192
#define NPC 256            // neurons per CTA
#define TPB 512
#define CLUSTER_N 2
#define TWO_PI 6.2831853071795864769f
#define INV_TWO_PI 0.15915494309189535f

// precomputed S[t] = sum_d x_t[d] * x_{t+1}[d]  (complex, plain product)
__device__ __align__(8) float2 Sbuf[TT];

// ---- packed f32x2 helpers (sm_100+) ----
__device__ __forceinline__ unsigned long long ffma2(unsigned long long a,
                                                    unsigned long long b,
                                                    unsigned long long c) {
    unsigned long long d;
    asm("fma.rn.f32x2 %0, %1, %2, %3;" : "=l"(d) : "l"(a), "l"(b), "l"(c));
    return d;
}
__device__ __forceinline__ unsigned long long pack2(float lo, float hi) {
    unsigned long long r;
    asm("mov.b64 %0, {%1, %2};" : "=l"(r) : "f"(lo), "f"(hi));
    return r;
}
__device__ __forceinline__ void unpack2(unsigned long long v, float& lo, float& hi) {
    asm("mov.b64 {%0, %1}, %2;" : "=f"(lo), "=f"(hi) : "l"(v));
}
__device__ __forceinline__ float wrap2pi(float x) {
    return x - floorf(x * INV_TWO_PI) * TWO_PI;
}
__device__ __forceinline__ unsigned smem_u32(const void* p) {
    unsigned a;
    asm("{ .reg .u64 t; cvta.to.shared.u64 t, %1; cvt.u32.u64 %0, t; }"
        : "=r"(a) : "l"(p));
    return a;
}
__device__ __forceinline__ unsigned cluster_rank() {
    unsigned r;
    asm("mov.u32 %0, %%cluster_ctarank;" : "=r"(r));
    return r;
}
__device__ __forceinline__ void mb_init(unsigned a, unsigned cnt) {
    asm volatile("mbarrier.init.shared.b64 [%0], %1;" :: "r"(a), "r"(cnt) : "memory");
}
// store my partial into peer's buf + arrive on peer's mbarrier (tid0 only)
__device__ __forceinline__ void push_partial(unsigned bufaddr, float v,
                                             unsigned mbaddr, unsigned peer) {
    unsigned vb = __float_as_uint(v);
    asm volatile("{\n\t"
        ".reg .b32 rb, rm;\n\t"
        "mapa.shared::cluster.u32 rb, %0, %1;\n\t"
        "st.shared::cluster.b32 [rb], %2;\n\t"
        "fence.acq_rel.cluster;\n\t"
        "mapa.shared::cluster.u32 rm, %3, %1;\n\t"
        "mbarrier.arrive.shared::cluster.b64 _, [rm];\n\t"
        "}" :: "r"(bufaddr), "r"(peer), "r"(vb), "r"(mbaddr) : "memory");
}
__device__ __forceinline__ void mb_wait_par(unsigned a, unsigned par) {
    unsigned done;
    asm volatile("{\n\t"
        ".reg .pred p;\n\t"
        "mbarrier.try_wait.parity.acquire.cta.shared::cta.b64 p, [%1], %2;\n\t"
        "selp.b32 %0, 1, 0, p;\n\t"
        "}" : "=r"(done) : "r"(a), "r"(par) : "memory");
    if (!done) {
        asm volatile("{\n\t"
            ".reg .pred P1;\n\t"
            "W_%=:\n\t"
            "mbarrier.try_wait.parity.acquire.cta.shared::cta.b64 P1, [%0], %1, 0x989680;\n\t"
            "@P1 bra D_%=;\n\t"
            "bra W_%=;\n\t"
            "D_%=:\n\t"
            "}" :: "r"(a), "r"(par) : "memory");
    }
    asm volatile("fence.acq_rel.cluster;" ::: "memory");
}

// half-matvec over this thread's 16 d's. xaRow = row base (33 float4 entries,
// halves padded apart by 16B to avoid bank conflicts). hf in {0,1}.
__device__ __forceinline__ void cmatvec_h(const unsigned long long* __restrict__ w2,
                                          const float4* __restrict__ xaRow, int hf,
                                          float& zr, float& zi) {
    unsigned long long a0 = 0ull, a1 = 0ull, b0 = 0ull, b1 = 0ull;
    const ulonglong2* xa = (const ulonglong2*)xaRow + hf * 17;
#pragma unroll
    for (int j = 0; j < HD; j += 2) {
        ulonglong2 v0 = xa[j];
        ulonglong2 v1 = xa[j + 1];
        a0 = ffma2(w2[j],     v0.x, a0);   // (Σwr·xr, Σwi·xr)
        b0 = ffma2(w2[j],     v0.y, b0);   // (Σwr·xi, Σwi·xi)
        a1 = ffma2(w2[j + 1], v1.x, a1);
        b1 = ffma2(w2[j + 1], v1.y, b1);
    }
    float a0l, a0h, a1l, a1h, b0l, b0h, b1l, b1h;
    unpack2(a0, a0l, a0h); unpack2(a1, a1l, a1h);
    unpack2(b0, b0l, b0h); unpack2(b1, b1l, b1h);
    float ar = a0l + a1l, ai = a0h + a1h;
    float br = b0l + b1l, bi = b0h + b1h;
    zr = ar - bi;
    zi = br + ai;
}

// ---- parallel pre-kernel: S[t] for all t ----
__global__ void precomp_s(const float* __restrict__ Xr, const float* __restrict__ Xi) {
    int t = blockIdx.x * 256 + threadIdx.x;
    if (t >= TT) return;
    float sr = 0.f, si = 0.f;
    if (t + 1 < TT) {
        const float4* cr = (const float4*)(Xr + t * DD);
        const float4* ci = (const float4*)(Xi + t * DD);
        const float4* nr = (const float4*)(Xr + (t + 1) * DD);
        const float4* ni = (const float4*)(Xi + (t + 1) * DD);
#pragma unroll
        for (int j = 0; j < DD / 4; j++) {
            float4 a = cr[j], b = ci[j], c = nr[j], d = ni[j];
            sr += a.x * c.x - b.x * d.x;  si += a.x * d.x + b.x * c.x;
            sr += a.y * c.y - b.y * d.y;  si += a.y * d.y + b.y * c.y;
            sr += a.z * c.z - b.z * d.z;  si += a.z * d.z + b.z * c.z;
            sr += a.w * c.w - b.w * d.w;  si += a.w * d.w + b.w * c.w;
        }
    }
    Sbuf[t] = make_float2(sr, si);
}

__global__ __launch_bounds__(TPB, 1) __cluster_dims__(CLUSTER_N, 1, 1)
void rds_kernel(const float* __restrict__ Xr, const float* __restrict__ Xi,
                const float* __restrict__ tw, const float* __restrict__ Wr,
                const float* __restrict__ Wi, const float* __restrict__ phi0,
                const float* __restrict__ beta0, float* __restrict__ out) {
    const int tid  = threadIdx.x;
    const int lane = tid & 31;
    const int wid  = tid >> 5;            // 0..15
    const int hf   = tid & 1;             // d-half
    const unsigned rank = cluster_rank();
    const unsigned peer = rank ^ 1u;
    const int g = rank * NPC + (tid >> 1);  // global neuron

    // 4-way buffered x; halves padded 16B apart (bank-conflict-free d-split)
    __shared__ __align__(16) float4 xsA[4][2 * HD + 1];   // (xr,xr,xi,xi)
    __shared__ __align__(16) float  xsB[4][2 * DD + 4];   // interleaved (xr,xi)
    __shared__ float s_tgt[4];
    __shared__ __align__(16) float red[2][16];
    __shared__ __align__(8) unsigned long long mb[2];
    __shared__ float peerbuf[2];

    const unsigned mb0_a  = smem_u32(&mb[0]);
    const unsigned mb1_a  = smem_u32(&mb[1]);
    const unsigned pb0_a  = smem_u32(&peerbuf[0]);
    const unsigned pb1_a  = smem_u32(&peerbuf[1]);

    // this thread's 16 W entries
    unsigned long long w2[HD];
#pragma unroll
    for (int k = 0; k < HD; k++)
        w2[k] = pack2(Wr[g * DD + hf * HD + k], Wi[g * DD + hf * HD + k]);

    float phi  = phi0[g];
    float beta = beta0[g];
    float lt   = 0.0f;
    float err  = 0.0f;

    float* outs   = out;
    float* betas  = out + TT;
    float* gammas = out + TT + (size_t)TT * NN;

    // prologue: x_0 -> buf0, x_1 -> buf1 (writers tid<DD; pad halves apart)
    if (tid < DD) {
        int e = (tid < HD) ? tid : tid + 1;          // xsA entry
        int f = (tid < HD) ? 2 * tid : 2 * tid + 4;  // xsB float index
        float xr = Xr[tid], xi = Xi[tid];
        xsA[0][e] = make_float4(xr, xr, xi, xi);
        xsB[0][f] = xr; xsB[0][f + 1] = xi;
        xr = Xr[DD + tid]; xi = Xi[DD + tid];
        xsA[1][e] = make_float4(xr, xr, xi, xi);
        xsB[1][f] = xr; xsB[1][f + 1] = xi;
        if (tid == 0) { s_tgt[0] = tw[0]; s_tgt[1] = tw[1]; }
    }
    if (tid == 0) { mb_init(mb0_a, 1); mb_init(mb1_a, 1); }
    __syncthreads();
    // peer's mbarriers must be live before any remote arrive
    asm volatile("barrier.cluster.arrive.aligned;" ::: "memory");
    asm volatile("barrier.cluster.wait.aligned;" ::: "memory");

    // Z_0 = W_0 @ x_0 (half + partner combine)
    float zr, zi;
    cmatvec_h(w2, xsA[0], hf, zr, zi);
    zr += __shfl_xor_sync(0xffffffffu, zr, 1);
    zi += __shfl_xor_sync(0xffffffffu, zi, 1);

    // pipelined head for step 0
    float gamma = __expf(-0.5f * beta);
    float dtl   = gamma * 1e-3f;
    lt += dtl;
    float sn, cs;
    __sincosf(wrap2pi(10.0f * lt + phi), &sn, &cs);

#pragma unroll 1
    for (int t = 0; t < TT; t++) {
        const int b  = t & 3;
        const int bn = (t + 1) & 3;
        const int bp = (t + 2) & 3;
        const int rb = t & 1;
        const unsigned mba = rb ? mb1_a : mb0_a;
        const unsigned pba = rb ? pb1_a : pb0_a;
        const unsigned par = (t >> 1) & 1;

        // ================= PRE-BARRIER =================
        float dot = cs * zr + sn * zi;
        float Y   = fmaxf(dot, 0.0f);
        float v   = hf ? 0.0f : Y * cs;     // avoid pair double-count
#pragma unroll
        for (int o = 16; o; o >>= 1)
            v += __shfl_xor_sync(0xffffffffu, v, o);
        if (lane == 0) red[rb][wid] = v;

        // prefetch x_{t+2}, tgt_{t+2}
        if (tid < DD && t + 2 < TT) {
            int e = (tid < HD) ? tid : tid + 1;
            int f = (tid < HD) ? 2 * tid : 2 * tid + 4;
            float xr = Xr[(t + 2) * DD + tid];
            float xi = Xi[(t + 2) * DD + tid];
            xsA[bp][e] = make_float4(xr, xr, xi, xi);
            xsB[bp][f] = xr; xsB[bp][f + 1] = xi;
            if (tid == 0) s_tgt[bp] = tw[t + 2];
        }

        // U_t = W_t @ x_{t+1} (half + partner combine; off the scalar chain)
        float ur, ui;
        cmatvec_h(w2, xsA[bn], hf, ur, ui);
        ur += __shfl_xor_sync(0xffffffffu, ur, 1);
        ui += __shfl_xor_sync(0xffffffffu, ui, 1);

        float2 S  = __ldg(&Sbuf[t]);        // precomputed input dot
        float tgt = s_tgt[b];

        __syncthreads();

        // ================= POST-BARRIER =================
        // CTA partial: lane reads one of 16 warp partials, 4-level butterfly
        float p = red[rb][lane & 15];
#pragma unroll
        for (int o = 8; o; o >>= 1)
            p += __shfl_xor_sync(0xffffffffu, p, o);
        // exchange partials across the cluster
        if (tid == 0) push_partial(pba, p, mba, peer);
        mb_wait_par(mba, par);
        float out_v = p + peerbuf[rb];      // commutative -> identical in both CTAs

        // thermodynamic feedback (identical everywhere)
        err = 0.99f * err + 0.01f * fabsf(tgt - out_v);
        float rel  = __fdividef(err, fabsf(tgt) + 0.01f);
        float btgt = 3.5f * __expf(-5.0f * rel);
        float a_s  = (btgt > beta)
                   ? (1.0f - __expf(-2e-3f * (gamma + 1e-6f)))
                   : 0.03278394f;           // 1 - exp(-1/30)
        float bnew = beta + a_s * (btgt - beta);
        bnew = fminf(fmaxf(bnew, 0.005f), 5.0f);

        float gg  = 0.05f * Y * dtl;
        float ddc = bnew * Y * Y * dtl;
        unsigned long long g2  = pack2(gg, gg);
        unsigned long long nd2 = pack2(-ddc, -ddc);

        // Z_{t+1} = (1-ddc)*U + gg*S
        unsigned long long u2 = pack2(ur, ui);
        unsigned long long z2 = ffma2(g2, pack2(S.x, S.y), ffma2(nd2, u2, u2));
        unpack2(z2, zr, zi);

        // outputs
        if (hf == 0) {
            betas[t * NN + g]  = bnew;
            gammas[t * NN + g] = gamma;
        }
        if (rank == 0 && tid == 0) outs[t] = out_v;

        // phase pull + wrap
        float phin = phi + (2.0f / 512.0f) * (-tgt * sn) * dtl;
        phin -= floorf(phin * INV_TWO_PI) * TWO_PI;

        // pipelined head of next step
        float gamman = __expf(-0.5f * bnew);
        float dtln   = gamman * 1e-3f;
        float ltn    = lt + dtln;
        float snn, csn;
        __sincosf(wrap2pi(10.0f * ltn + phin), &snn, &csn);

        // W update over this thread's 16 d's (8 padded ulonglong2)
        {
            const ulonglong2* xb = (const ulonglong2*)xsB[b] + (hf ? 9 : 0);
#pragma unroll
            for (int j = 0; j < HD / 2; j++) {
                ulonglong2 u = xb[j];
                w2[2 * j]     = ffma2(g2, u.x, ffma2(nd2, w2[2 * j],     w2[2 * j]));
                w2[2 * j + 1] = ffma2(g2, u.y, ffma2(nd2, w2[2 * j + 1], w2[2 * j + 1]));
            }
        }

        beta  = bnew;
        phi   = phin;
        gamma = gamman;
        dtl   = dtln;
        lt    = ltn;
        sn    = snn;
        cs    = csn;
    }

    // no CTA may exit while peer remote ops could still target its smem
    asm volatile("barrier.cluster.arrive.aligned;" ::: "memory");
    asm volatile("barrier.cluster.wait.aligned;" ::: "memory");
}

extern "C" void kernel_launch(void* const* d_in, const int* in_sizes, int n_in,
                              void* d_out, int out_size) {
    const float* Xr    = (const float*)d_in[0];
    const float* Xi    = (const float*)d_in[1];
    const float* tw    = (const float*)d_in[2];
    const float* Wr    = (const float*)d_in[3];
    const float* Wi    = (const float*)d_in[4];
    const float* phi0  = (const float*)d_in[5];
    const float* beta0 = (const float*)d_in[6];
    float* out = (float*)d_out;
    precomp_s<<<TT / 256, 256>>>(Xr, Xi);
    rds_kernel<<<CLUSTER_N, TPB>>>(Xr, Xi, tw, Wr, Wi, phi0, beta0, out);
}

// round 10
// speedup vs baseline: 1.6036x; 1.6036x over previous
#include <cuda_runtime.h>

#define NN 512
#define DD 32
#define TT 8192
#define TPB 256            // 2 neurons per thread
#define TWO_PI 6.2831853071795864769f
#define INV_TWO_PI 0.15915494309189535f

// precomputed S[t] = sum_d x_t[d] * x_{t+1}[d]  (complex)
__device__ __align__(8) float2 Sbuf[TT];

// ---- packed f32x2 helpers (sm_100+) ----
__device__ __forceinline__ unsigned long long ffma2(unsigned long long a,
                                                    unsigned long long b,
                                                    unsigned long long c) {
    unsigned long long d;
    asm("fma.rn.f32x2 %0, %1, %2, %3;" : "=l"(d) : "l"(a), "l"(b), "l"(c));
    return d;
}
__device__ __forceinline__ unsigned long long pack2(float lo, float hi) {
    unsigned long long r;
    asm("mov.b64 %0, {%1, %2};" : "=l"(r) : "f"(lo), "f"(hi));
    return r;
}
__device__ __forceinline__ void unpack2(unsigned long long v, float& lo, float& hi) {
    asm("mov.b64 {%0, %1}, %2;" : "=f"(lo), "=f"(hi) : "l"(v));
}
__device__ __forceinline__ float wrap2pi(float x) {
    return x - floorf(x * INV_TWO_PI) * TWO_PI;
}

// ---- parallel pre-kernel: S[t] for all t ----
__global__ void precomp_s(const float* __restrict__ Xr, const float* __restrict__ Xi) {
    int t = blockIdx.x * 256 + threadIdx.x;
    if (t >= TT) return;
    float sr = 0.f, si = 0.f;
    if (t + 1 < TT) {
        const float4* cr = (const float4*)(Xr + t * DD);
        const float4* ci = (const float4*)(Xi + t * DD);
        const float4* nr = (const float4*)(Xr + (t + 1) * DD);
        const float4* ni = (const float4*)(Xi + (t + 1) * DD);
#pragma unroll
        for (int j = 0; j < DD / 4; j++) {
            float4 a = cr[j], b = ci[j], c = nr[j], d = ni[j];
            sr += a.x * c.x - b.x * d.x;  si += a.x * d.x + b.x * c.x;
            sr += a.y * c.y - b.y * d.y;  si += a.y * d.y + b.y * c.y;
            sr += a.z * c.z - b.z * d.z;  si += a.z * d.z + b.z * c.z;
            sr += a.w * c.w - b.w * d.w;  si += a.w * d.w + b.w * c.w;
        }
    }
    Sbuf[t] = make_float2(sr, si);
}

__global__ __launch_bounds__(TPB, 1)
void rds_kernel(const float* __restrict__ Xr, const float* __restrict__ Xi,
                const float* __restrict__ tw, const float* __restrict__ Wr,
                const float* __restrict__ Wi, const float* __restrict__ phi0,
                const float* __restrict__ beta0, float* __restrict__ out) {
    const int tid  = threadIdx.x;
    const int lane = tid & 31;
    const int wid  = tid >> 5;              // 0..7

    // 4-way buffered per-step shared state
    __shared__ __align__(16) float4 xsA[4][DD];     // (xr,xr,xi,xi) per d
    __shared__ __align__(16) float  xsB[4][2 * DD]; // interleaved (xr,xi)
    __shared__ float  s_tgt[4];
    __shared__ __align__(16) float red[2][8];       // per-warp partials

    // factored W: W = alpha * A ; A packed (ar,ai) per d, per neuron
    unsigned long long A[2][DD];            // 128 regs
    float alpha[2] = {1.0f, 1.0f};
    float phi[2], beta[2], lt[2], gamma[2], dtl[2], sn[2], cs[2];
    float zr[2], zi[2];
    float err = 0.0f;                       // identical in every thread

#pragma unroll
    for (int n = 0; n < 2; n++) {
        const int g = tid + n * TPB;
#pragma unroll
        for (int d = 0; d < DD; d++)
            A[n][d] = pack2(Wr[g * DD + d], Wi[g * DD + d]);
        phi[n]  = phi0[g];
        beta[n] = beta0[g];
        lt[n]   = 0.0f;
    }

    float* outs   = out;
    float* betas  = out + TT;
    float* gammas = out + TT + (size_t)TT * NN;

    // prologue: x_0 -> buf0, x_1 -> buf1
    if (tid < DD) {
        float xr = Xr[tid], xi = Xi[tid];
        xsA[0][tid] = make_float4(xr, xr, xi, xi);
        xsB[0][2 * tid] = xr; xsB[0][2 * tid + 1] = xi;
        xr = Xr[DD + tid]; xi = Xi[DD + tid];
        xsA[1][tid] = make_float4(xr, xr, xi, xi);
        xsB[1][2 * tid] = xr; xsB[1][2 * tid + 1] = xi;
        if (tid == 0) { s_tgt[0] = tw[0]; s_tgt[1] = tw[1]; }
    }

    // pipelined head for step 0
#pragma unroll
    for (int n = 0; n < 2; n++) {
        gamma[n] = __expf(-0.5f * beta[n]);
        dtl[n]   = gamma[n] * 1e-3f;
        lt[n]   += dtl[n];
        __sincosf(wrap2pi(10.0f * lt[n] + phi[n]), &sn[n], &cs[n]);
    }

    __syncthreads();

    // Z_0 = A @ x_0 (alpha = 1), both neurons fused over shared x loads
    {
        unsigned long long aA0 = 0ull, aB0 = 0ull, aA1 = 0ull, aB1 = 0ull;
        const ulonglong2* xa = (const ulonglong2*)xsA[0];
#pragma unroll
        for (int d = 0; d < DD; d++) {
            ulonglong2 v = xa[d];
            aA0 = ffma2(A[0][d], v.x, aA0);
            aB0 = ffma2(A[0][d], v.y, aB0);
            aA1 = ffma2(A[1][d], v.x, aA1);
            aB1 = ffma2(A[1][d], v.y, aB1);
        }
        float a0l, a0h, b0l, b0h, a1l, a1h, b1l, b1h;
        unpack2(aA0, a0l, a0h); unpack2(aB0, b0l, b0h);
        unpack2(aA1, a1l, a1h); unpack2(aB1, b1l, b1h);
        zr[0] = a0l - b0h;  zi[0] = b0l + a0h;
        zr[1] = a1l - b1h;  zi[1] = b1l + a1h;
    }

#pragma unroll 1
    for (int t = 0; t < TT; t++) {
        const int b  = t & 3;
        const int bn = (t + 1) & 3;
        const int bp = (t + 2) & 3;
        const int rb = t & 1;

        // ================= PRE-BARRIER =================
        float Y[2], v = 0.0f;
#pragma unroll
        for (int n = 0; n < 2; n++) {
            float dot = cs[n] * zr[n] + sn[n] * zi[n];
            Y[n] = fmaxf(dot, 0.0f);
            v += Y[n] * cs[n];
        }
#pragma unroll
        for (int o = 16; o; o >>= 1)
            v += __shfl_xor_sync(0xffffffffu, v, o);
        if (lane == 0) red[rb][wid] = v;

        // prefetch x_{t+2}, tgt_{t+2}
        if (tid < DD && t + 2 < TT) {
            float xr = Xr[(t + 2) * DD + tid];
            float xi = Xi[(t + 2) * DD + tid];
            xsA[bp][tid] = make_float4(xr, xr, xi, xi);
            xsB[bp][2 * tid]     = xr;
            xsB[bp][2 * tid + 1] = xi;
            if (tid == 0) s_tgt[bp] = tw[t + 2];
        }

        // U = A @ x_{t+1}, both neurons fused (shared x loads)
        float ur[2], ui[2];
        {
            unsigned long long aA0 = 0ull, aB0 = 0ull, aA1 = 0ull, aB1 = 0ull;
            const ulonglong2* xa = (const ulonglong2*)xsA[bn];
#pragma unroll
            for (int d = 0; d < DD; d++) {
                ulonglong2 vv = xa[d];
                aA0 = ffma2(A[0][d], vv.x, aA0);
                aB0 = ffma2(A[0][d], vv.y, aB0);
                aA1 = ffma2(A[1][d], vv.x, aA1);
                aB1 = ffma2(A[1][d], vv.y, aB1);
            }
            float a0l, a0h, b0l, b0h, a1l, a1h, b1l, b1h;
            unpack2(aA0, a0l, a0h); unpack2(aB0, b0l, b0h);
            unpack2(aA1, a1l, a1h); unpack2(aB1, b1l, b1h);
            ur[0] = a0l - b0h;  ui[0] = b0l + a0h;
            ur[1] = a1l - b1h;  ui[1] = b1l + a1h;
        }

        float2 S  = __ldg(&Sbuf[t]);
        float tgt = s_tgt[b];

        __syncthreads();   // the single per-step barrier

        // ================= POST-BARRIER =================
        float4 r0 = *(const float4*)&red[rb][0];
        float4 r1 = *(const float4*)&red[rb][4];
        float out_v = ((r0.x + r0.y) + (r0.z + r0.w))
                    + ((r1.x + r1.y) + (r1.z + r1.w));

        // shared scalar feedback (identical in all threads)
        err = 0.99f * err + 0.01f * fabsf(tgt - out_v);
        float rel  = __fdividef(err, fabsf(tgt) + 0.01f);
        float btgt = 3.5f * __expf(-5.0f * rel);

        unsigned long long cpk[2];
#pragma unroll
        for (int n = 0; n < 2; n++) {
            float a_s  = (btgt > beta[n])
                       ? (1.0f - __expf(-2e-3f * (gamma[n] + 1e-6f)))
                       : 0.03278394f;   // 1 - exp(-1/30)
            float bnew = beta[n] + a_s * (btgt - beta[n]);
            bnew = fminf(fmaxf(bnew, 0.005f), 5.0f);

            float gg  = 0.05f * Y[n] * dtl[n];
            float ddc = bnew * Y[n] * Y[n] * dtl[n];
            float one = 1.0f - ddc;

            // Z_{t+1} = one * (alpha * U) + gg * S
            float au = one * alpha[n];
            zr[n] = au * ur[n] + gg * S.x;
            zi[n] = au * ui[n] + gg * S.y;

            // factored W update: alpha' = alpha*one ; A += (gg/alpha')*x_t
            float an = alpha[n] * one;
            float c  = __fdividef(gg, an);
            alpha[n] = an;
            cpk[n]   = pack2(c, c);

            // outputs
            const int g = tid + n * TPB;
            betas[t * NN + g]  = bnew;
            gammas[t * NN + g] = gamma[n];

            // phase pull + wrap
            float phin = phi[n] + (2.0f / 512.0f) * (-tgt * sn[n]) * dtl[n];
            phin -= floorf(phin * INV_TWO_PI) * TWO_PI;
            phi[n] = phin;

            // pipelined head of next step
            beta[n]  = bnew;
            gamma[n] = __expf(-0.5f * bnew);
            dtl[n]   = gamma[n] * 1e-3f;
            lt[n]   += dtl[n];
            __sincosf(wrap2pi(10.0f * lt[n] + phin), &sn[n], &cs[n]);
        }
        if (tid == 0) outs[t] = out_v;

        // A update, both neurons fused (shared x_t loads)
        {
            const ulonglong2* xb = (const ulonglong2*)xsB[b];
#pragma unroll
            for (int j = 0; j < DD / 2; j++) {
                ulonglong2 u = xb[j];
                A[0][2 * j]     = ffma2(cpk[0], u.x, A[0][2 * j]);
                A[0][2 * j + 1] = ffma2(cpk[0], u.y, A[0][2 * j + 1]);
                A[1][2 * j]     = ffma2(cpk[1], u.x, A[1][2 * j]);
                A[1][2 * j + 1] = ffma2(cpk[1], u.y, A[1][2 * j + 1]);
            }
        }

        // periodic renormalization: fold alpha into A
        if ((t & 127) == 127) {
#pragma unroll
            for (int n = 0; n < 2; n++) {
                unsigned long long apk = pack2(alpha[n], alpha[n]);
#pragma unroll
                for (int d = 0; d < DD; d++)
                    A[n][d] = ffma2(apk, A[n][d], 0ull);
                alpha[n] = 1.0f;
            }
        }
    }
}

extern "C" void kernel_launch(void* const* d_in, const int* in_sizes, int n_in,
                              void* d_out, int out_size) {
    const float* Xr    = (const float*)d_in[0];
    const float* Xi    = (const float*)d_in[1];
    const float* tw    = (const float*)d_in[2];
    const float* Wr    = (const float*)d_in[3];
    const float* Wi    = (const float*)d_in[4];
    const float* phi0  = (const float*)d_in[5];
    const float* beta0 = (const float*)d_in[6];
    float* out = (float*)d_out;
    precomp_s<<<TT / 256, 256>>>(Xr, Xi);
    rds_kernel<<<1, TPB>>>(Xr, Xi, tw, Wr, Wi, phi0, beta0, out);
}